// round 3
// baseline (speedup 1.0000x reference)
#include <cuda_runtime.h>
#include <math.h>

#define NE 8
#define DIM 1024
#define HID 1024
#define NTOK 4096
#define NSLOT (NTOK * 2)
#define SLOT_PAD (NSLOT + 128)

#define BM 128
#define BN 128
#define BK 8

// ---- scratch (device globals: zero-initialized at module load, no allocs) ----
__device__ float g_act[(size_t)SLOT_PAD * HID];    // post-GELU activations per slot
__device__ float g_part[(size_t)SLOT_PAD * DIM];   // per-slot gated partial outputs
__device__ int   g_slot_token[SLOT_PAD];
__device__ float g_slot_gate[SLOT_PAD];
__device__ int   g_counts[NE];
__device__ int   g_cursor[NE];
__device__ int   g_offsets[NE + 1];
__device__ int   g_top_e[NSLOT];
__device__ float g_top_w[NSLOT];
__device__ int   g_token_slot[NSLOT];

// ---- reset per-launch counters (graph replays reuse state) ----
__global__ void zero_kernel() {
    int i = threadIdx.x;
    if (i < NE) { g_counts[i] = 0; g_cursor[i] = 0; }
}

// ---- gating: logits = x@wg, softmax, top-2, renorm; count per expert ----
__global__ void gating_kernel(const float* __restrict__ x, const float* __restrict__ wg) {
    __shared__ float swg[DIM * NE];
    int tid = threadIdx.x;
    for (int i = tid; i < DIM * NE / 4; i += 256)
        ((float4*)swg)[i] = ((const float4*)wg)[i];
    __syncthreads();

    int warp = tid >> 5, lane = tid & 31;
    int t = blockIdx.x * 8 + warp;
    const float* xr = x + (size_t)t * DIM;

    float acc[NE];
#pragma unroll
    for (int e = 0; e < NE; e++) acc[e] = 0.f;

    for (int d = lane; d < DIM; d += 32) {
        float xv = xr[d];
#pragma unroll
        for (int e = 0; e < NE; e++) acc[e] += xv * swg[d * NE + e];
    }
#pragma unroll
    for (int e = 0; e < NE; e++) {
#pragma unroll
        for (int o = 16; o > 0; o >>= 1)
            acc[e] += __shfl_down_sync(0xffffffffu, acc[e], o);
    }
    if (lane == 0) {
        float mx = acc[0];
#pragma unroll
        for (int e = 1; e < NE; e++) mx = fmaxf(mx, acc[e]);
        float Z = 0.f;
#pragma unroll
        for (int e = 0; e < NE; e++) { acc[e] = expf(acc[e] - mx); Z += acc[e]; }
        float inv = 1.f / Z;
        float v1 = -1.f, v2 = -1.f; int i1 = 0, i2 = 0;
#pragma unroll
        for (int e = 0; e < NE; e++) {
            float p = acc[e] * inv;
            if (p > v1)      { v2 = v1; i2 = i1; v1 = p; i1 = e; }
            else if (p > v2) { v2 = p;  i2 = e; }
        }
        float den = v1 + v2 + 1e-6f;
        g_top_e[t * 2]     = i1;
        g_top_e[t * 2 + 1] = i2;
        g_top_w[t * 2]     = v1 / den;
        g_top_w[t * 2 + 1] = v2 / den;
        atomicAdd(&g_counts[i1], 1);
        atomicAdd(&g_counts[i2], 1);
    }
}

__global__ void scan_kernel() {
    if (threadIdx.x == 0) {
        int s = 0;
        for (int e = 0; e < NE; e++) { g_offsets[e] = s; s += g_counts[e]; }
        g_offsets[NE] = s;
    }
}

__global__ void build_kernel() {
    int i = blockIdx.x * blockDim.x + threadIdx.x;
    if (i >= NSLOT) return;
    int t = i >> 1;
    int e = g_top_e[i];
    int pos = atomicAdd(&g_cursor[e], 1);
    int slot = g_offsets[e] + pos;
    g_slot_token[slot] = t;
    g_slot_gate[slot]  = g_top_w[i];
    g_token_slot[i]    = slot;
}

// ---- GEMM1: act[slot, :] = gelu( x[token[slot]] @ w1[e] + b1[e] ) ----
__global__ __launch_bounds__(256, 2)
void gemm1_kernel(const float* __restrict__ x, const float* __restrict__ w1,
                  const float* __restrict__ b1) {
    int e = blockIdx.z;
    int off = g_offsets[e];
    int cnt = g_offsets[e + 1] - off;
    int row0 = blockIdx.y * BM;
    if (row0 >= cnt) return;
    int rows = cnt - row0; if (rows > BM) rows = BM;
    int n0 = blockIdx.x * BN;

    __shared__ float As[2][BK][BM];
    __shared__ float Bs[2][BK][BN];
    __shared__ int   stok[BM];

    int tid = threadIdx.x;
    if (tid < BM)
        stok[tid] = g_slot_token[off + row0 + ((tid < rows) ? tid : 0)];
    __syncthreads();

    const float* Bp = w1 + (size_t)e * DIM * HID;

    int ar  = tid >> 1;
    int ak  = (tid & 1) * 4;
    int bkr = tid >> 5;
    int bn  = (tid & 31) * 4;
    const float* arow = x + (size_t)stok[ar] * DIM + ak;

    int ty = tid >> 4, tx = tid & 15;

    float acc[8][8];
#pragma unroll
    for (int i = 0; i < 8; i++)
#pragma unroll
        for (int j = 0; j < 8; j++) acc[i][j] = 0.f;

    float4 a_reg = *(const float4*)(arow);
    float4 b_reg = *(const float4*)(Bp + (size_t)bkr * HID + n0 + bn);
    As[0][ak + 0][ar] = a_reg.x; As[0][ak + 1][ar] = a_reg.y;
    As[0][ak + 2][ar] = a_reg.z; As[0][ak + 3][ar] = a_reg.w;
    *(float4*)&Bs[0][bkr][bn] = b_reg;
    __syncthreads();

    int buf = 0;
    for (int k0 = BK; k0 <= DIM; k0 += BK) {
        if (k0 < DIM) {
            a_reg = *(const float4*)(arow + k0);
            b_reg = *(const float4*)(Bp + (size_t)(k0 + bkr) * HID + n0 + bn);
        }
#pragma unroll
        for (int k = 0; k < BK; k++) {
            float ra[8], rb[8];
#pragma unroll
            for (int i = 0; i < 8; i++) ra[i] = As[buf][k][ty * 8 + i];
#pragma unroll
            for (int j = 0; j < 8; j++) rb[j] = Bs[buf][k][tx * 8 + j];
#pragma unroll
            for (int i = 0; i < 8; i++)
#pragma unroll
                for (int j = 0; j < 8; j++)
                    acc[i][j] += ra[i] * rb[j];
        }
        if (k0 < DIM) {
            buf ^= 1;
            As[buf][ak + 0][ar] = a_reg.x; As[buf][ak + 1][ar] = a_reg.y;
            As[buf][ak + 2][ar] = a_reg.z; As[buf][ak + 3][ar] = a_reg.w;
            *(float4*)&Bs[buf][bkr][bn] = b_reg;
            __syncthreads();
        }
    }

    float bias[8];
#pragma unroll
    for (int j = 0; j < 8; j++) bias[j] = b1[e * HID + n0 + tx * 8 + j];

#pragma unroll
    for (int i = 0; i < 8; i++) {
        int r = ty * 8 + i;
        if (r < rows) {
            float* orow = g_act + (size_t)(off + row0 + r) * HID + n0 + tx * 8;
            float vj[8];
#pragma unroll
            for (int j = 0; j < 8; j++) {
                float h = acc[i][j] + bias[j];
                vj[j] = 0.5f * h * (1.f + erff(h * 0.70710678118654752f));
            }
            *(float4*)(orow)     = make_float4(vj[0], vj[1], vj[2], vj[3]);
            *(float4*)(orow + 4) = make_float4(vj[4], vj[5], vj[6], vj[7]);
        }
    }
}

// ---- GEMM2: part[slot, :] = gate[slot] * ( act[slot] @ w2[e] + b2[e] ) ----
__global__ __launch_bounds__(256, 2)
void gemm2_kernel(const float* __restrict__ w2, const float* __restrict__ b2) {
    int e = blockIdx.z;
    int off = g_offsets[e];
    int cnt = g_offsets[e + 1] - off;
    int row0 = blockIdx.y * BM;
    if (row0 >= cnt) return;
    int rows = cnt - row0; if (rows > BM) rows = BM;
    int n0 = blockIdx.x * BN;

    __shared__ float As[2][BK][BM];
    __shared__ float Bs[2][BK][BN];
    __shared__ float sgate[BM];

    int tid = threadIdx.x;
    if (tid < BM)
        sgate[tid] = g_slot_gate[off + row0 + ((tid < rows) ? tid : 0)];
    __syncthreads();

    const float* Bp = w2 + (size_t)e * HID * DIM;

    int ar  = tid >> 1;
    int ak  = (tid & 1) * 4;
    int bkr = tid >> 5;
    int bn  = (tid & 31) * 4;
    const float* arow = g_act + (size_t)(off + row0 + ar) * HID + ak;

    int ty = tid >> 4, tx = tid & 15;

    float acc[8][8];
#pragma unroll
    for (int i = 0; i < 8; i++)
#pragma unroll
        for (int j = 0; j < 8; j++) acc[i][j] = 0.f;

    float4 a_reg = *(const float4*)(arow);
    float4 b_reg = *(const float4*)(Bp + (size_t)bkr * DIM + n0 + bn);
    As[0][ak + 0][ar] = a_reg.x; As[0][ak + 1][ar] = a_reg.y;
    As[0][ak + 2][ar] = a_reg.z; As[0][ak + 3][ar] = a_reg.w;
    *(float4*)&Bs[0][bkr][bn] = b_reg;
    __syncthreads();

    int buf = 0;
    for (int k0 = BK; k0 <= HID; k0 += BK) {
        if (k0 < HID) {
            a_reg = *(const float4*)(arow + k0);
            b_reg = *(const float4*)(Bp + (size_t)(k0 + bkr) * DIM + n0 + bn);
        }
#pragma unroll
        for (int k = 0; k < BK; k++) {
            float ra[8], rb[8];
#pragma unroll
            for (int i = 0; i < 8; i++) ra[i] = As[buf][k][ty * 8 + i];
#pragma unroll
            for (int j = 0; j < 8; j++) rb[j] = Bs[buf][k][tx * 8 + j];
#pragma unroll
            for (int i = 0; i < 8; i++)
#pragma unroll
                for (int j = 0; j < 8; j++)
                    acc[i][j] += ra[i] * rb[j];
        }
        if (k0 < HID) {
            buf ^= 1;
            As[buf][ak + 0][ar] = a_reg.x; As[buf][ak + 1][ar] = a_reg.y;
            As[buf][ak + 2][ar] = a_reg.z; As[buf][ak + 3][ar] = a_reg.w;
            *(float4*)&Bs[buf][bkr][bn] = b_reg;
            __syncthreads();
        }
    }

    float bias[8];
#pragma unroll
    for (int j = 0; j < 8; j++) bias[j] = b2[e * DIM + n0 + tx * 8 + j];

#pragma unroll
    for (int i = 0; i < 8; i++) {
        int r = ty * 8 + i;
        if (r < rows) {
            float gate = sgate[r];
            float* orow = g_part + (size_t)(off + row0 + r) * DIM + n0 + tx * 8;
            float vj[8];
#pragma unroll
            for (int j = 0; j < 8; j++)
                vj[j] = (acc[i][j] + bias[j]) * gate;
            *(float4*)(orow)     = make_float4(vj[0], vj[1], vj[2], vj[3]);
            *(float4*)(orow + 4) = make_float4(vj[4], vj[5], vj[6], vj[7]);
        }
    }
}

// ---- combine: y[t] = part[slot0(t)] + part[slot1(t)]  (deterministic) ----
__global__ void combine_kernel(float* __restrict__ y) {
    int i = blockIdx.x * blockDim.x + threadIdx.x;   // over NTOK*DIM/4
    int t  = i >> 8;            // DIM/4 = 256 float4 per token
    int d4 = i & 255;
    int s0 = g_token_slot[t * 2];
    int s1 = g_token_slot[t * 2 + 1];
    const float4* p = (const float4*)g_part;
    float4 a = p[(size_t)s0 * 256 + d4];
    float4 b = p[(size_t)s1 * 256 + d4];
    ((float4*)y)[i] = make_float4(a.x + b.x, a.y + b.y, a.z + b.z, a.w + b.w);
}

extern "C" void kernel_launch(void* const* d_in, const int* in_sizes, int n_in,
                              void* d_out, int out_size) {
    const float* x  = (const float*)d_in[0];
    const float* w1 = (const float*)d_in[1];
    const float* b1 = (const float*)d_in[2];
    const float* w2 = (const float*)d_in[3];
    const float* b2 = (const float*)d_in[4];
    const float* wg = (const float*)d_in[5];
    float* y = (float*)d_out;

    zero_kernel<<<1, 32>>>();
    gating_kernel<<<NTOK / 8, 256>>>(x, wg);
    scan_kernel<<<1, 1>>>();
    build_kernel<<<NSLOT / 256, 256>>>();

    dim3 g1(HID / BN, NSLOT / BM, NE);   // (8, 64, 8) worst-case static grid
    gemm1_kernel<<<g1, 256>>>(x, w1, b1);

    dim3 g2(DIM / BN, NSLOT / BM, NE);
    gemm2_kernel<<<g2, 256>>>(w2, b2);

    combine_kernel<<<NTOK * DIM / 4 / 256, 256>>>(y);
}

// round 4
// speedup vs baseline: 3.3957x; 3.3957x over previous
#include <cuda_runtime.h>
#include <cuda_bf16.h>
#include <math.h>
#include <stdint.h>

#define NE 8
#define DIM 1024
#define HID 1024
#define NTOK 4096
#define NSLOT (NTOK * 2)
#define SLOT_PAD (NSLOT + 128)
#define KX 2048            // packed K: [hi(1024) | lo(1024)]
#define BM 128
#define BN 128
#define BKS 32             // bf16 K per stage
#define NSTAGE 96          // expanded K = 3*1024, / 32
#define APAD 40            // As row stride (bf16): bank-clean + 8B aligned
#define BPAD 136           // Bs row stride (bf16): bank-clean + 16B aligned

// ---- scratch (device globals; zero-init, no allocs) ----
__device__ __nv_bfloat16 g_xs[(size_t)NTOK * KX];
__device__ __nv_bfloat16 g_w1s[(size_t)NE * KX * HID];
__device__ __nv_bfloat16 g_w2s[(size_t)NE * KX * DIM];
__device__ __nv_bfloat16 g_acts[(size_t)SLOT_PAD * KX];
__device__ float g_part[(size_t)SLOT_PAD * DIM];
__device__ int   g_slot_token[SLOT_PAD];
__device__ float g_slot_gate[SLOT_PAD];
__device__ int   g_counts[NE];
__device__ int   g_cursor[NE];
__device__ int   g_offsets[NE + 1];
__device__ int   g_top_e[NSLOT];
__device__ float g_top_w[NSLOT];
__device__ int   g_token_slot[NSLOT];

__device__ __forceinline__ uint32_t s2u(const void* p) {
    return (uint32_t)__cvta_generic_to_shared(p);
}

// ---- reset counters (graph replays reuse state) ----
__global__ void zero_kernel() {
    int i = threadIdx.x;
    if (i < NE) { g_counts[i] = 0; g_cursor[i] = 0; }
}

// ---- gating: softmax(x@wg), top-2, renorm, per-expert counts ----
__global__ void gating_kernel(const float* __restrict__ x, const float* __restrict__ wg) {
    __shared__ float swg[DIM * NE];
    int tid = threadIdx.x;
    for (int i = tid; i < DIM * NE / 4; i += 256)
        ((float4*)swg)[i] = ((const float4*)wg)[i];
    __syncthreads();

    int warp = tid >> 5, lane = tid & 31;
    int t = blockIdx.x * 8 + warp;
    const float* xr = x + (size_t)t * DIM;

    float acc[NE];
#pragma unroll
    for (int e = 0; e < NE; e++) acc[e] = 0.f;
    for (int d = lane; d < DIM; d += 32) {
        float xv = xr[d];
#pragma unroll
        for (int e = 0; e < NE; e++) acc[e] += xv * swg[d * NE + e];
    }
#pragma unroll
    for (int e = 0; e < NE; e++) {
#pragma unroll
        for (int o = 16; o > 0; o >>= 1)
            acc[e] += __shfl_down_sync(0xffffffffu, acc[e], o);
    }
    if (lane == 0) {
        float mx = acc[0];
#pragma unroll
        for (int e = 1; e < NE; e++) mx = fmaxf(mx, acc[e]);
        float Z = 0.f;
#pragma unroll
        for (int e = 0; e < NE; e++) { acc[e] = expf(acc[e] - mx); Z += acc[e]; }
        float inv = 1.f / Z;
        float v1 = -1.f, v2 = -1.f; int i1 = 0, i2 = 0;
#pragma unroll
        for (int e = 0; e < NE; e++) {
            float p = acc[e] * inv;
            if (p > v1)      { v2 = v1; i2 = i1; v1 = p; i1 = e; }
            else if (p > v2) { v2 = p;  i2 = e; }
        }
        float den = v1 + v2 + 1e-6f;
        g_top_e[t * 2]     = i1;
        g_top_e[t * 2 + 1] = i2;
        g_top_w[t * 2]     = v1 / den;
        g_top_w[t * 2 + 1] = v2 / den;
        atomicAdd(&g_counts[i1], 1);
        atomicAdd(&g_counts[i2], 1);
    }
}

__global__ void scan_kernel() {
    if (threadIdx.x == 0) {
        int s = 0;
        for (int e = 0; e < NE; e++) { g_offsets[e] = s; s += g_counts[e]; }
        g_offsets[NE] = s;
    }
}

__global__ void build_kernel() {
    int i = blockIdx.x * blockDim.x + threadIdx.x;
    if (i >= NSLOT) return;
    int t = i >> 1;
    int e = g_top_e[i];
    int pos = atomicAdd(&g_cursor[e], 1);
    int slot = g_offsets[e] + pos;
    g_slot_token[slot] = t;
    g_slot_gate[slot]  = g_top_w[i];
    g_token_slot[i]    = slot;
}

// ---- split x into [hi | lo] bf16 ----
__global__ void split_x_kernel(const float* __restrict__ x) {
    int i = blockIdx.x * blockDim.x + threadIdx.x;   // over NTOK*DIM/4
    float4 v = ((const float4*)x)[i];
    int t = i >> 8;                // 256 float4 per row
    int k = (i & 255) * 4;
    float vv[4] = {v.x, v.y, v.z, v.w};
    __nv_bfloat16 h[4], l[4];
#pragma unroll
    for (int q = 0; q < 4; q++) {
        h[q] = __float2bfloat16(vv[q]);
        l[q] = __float2bfloat16(vv[q] - __bfloat162float(h[q]));
    }
    size_t base = (size_t)t * KX + k;
    *(__nv_bfloat162*)&g_xs[base]         = __halves2bfloat162(h[0], h[1]);
    *(__nv_bfloat162*)&g_xs[base + 2]     = __halves2bfloat162(h[2], h[3]);
    *(__nv_bfloat162*)&g_xs[base + 1024]  = __halves2bfloat162(l[0], l[1]);
    *(__nv_bfloat162*)&g_xs[base + 1026]  = __halves2bfloat162(l[2], l[3]);
}

// ---- split weights [E][1024][1024] into ws [E][hi(1024)|lo(1024)][1024] ----
template<int WHICH>
__global__ void split_w_kernel(const float* __restrict__ w) {
    __nv_bfloat16* ws = (WHICH == 1) ? g_w1s : g_w2s;
    int i = blockIdx.x * blockDim.x + threadIdx.x;   // over NE*1024*1024/4
    float4 v = ((const float4*)w)[i];
    int e = i >> 18;                 // 262144 float4 per expert
    int r = (i >> 8) & 1023;
    int n = (i & 255) * 4;
    float vv[4] = {v.x, v.y, v.z, v.w};
    __nv_bfloat16 h[4], l[4];
#pragma unroll
    for (int q = 0; q < 4; q++) {
        h[q] = __float2bfloat16(vv[q]);
        l[q] = __float2bfloat16(vv[q] - __bfloat162float(h[q]));
    }
    size_t base = ((size_t)e * KX + r) * 1024 + n;
    *(__nv_bfloat162*)&ws[base]     = __halves2bfloat162(h[0], h[1]);
    *(__nv_bfloat162*)&ws[base + 2] = __halves2bfloat162(h[2], h[3]);
    size_t lbase = base + (size_t)1024 * 1024;
    *(__nv_bfloat162*)&ws[lbase]     = __halves2bfloat162(l[0], l[1]);
    *(__nv_bfloat162*)&ws[lbase + 2] = __halves2bfloat162(l[2], l[3]);
}

// ---- tensor-core grouped GEMM over expanded K=3072 ([hi|lo|hi] x [hi|hi|lo]) ----
// FIRST:  acts = gelu( xs[token] @ w1s + b1 ), written split hi/lo
// !FIRST: part = gate * ( acts @ w2s + b2 )
template<bool FIRST>
__global__ __launch_bounds__(256, 2)
void moe_gemm(const float* __restrict__ bias) {
    int e = blockIdx.z;
    int off = g_offsets[e];
    int cnt = g_offsets[e + 1] - off;
    int row0 = blockIdx.y * BM;
    if (row0 >= cnt) return;
    int rows = cnt - row0; if (rows > BM) rows = BM;
    int n0 = blockIdx.x * BN;

    const __nv_bfloat16* Ag = FIRST ? g_xs : g_acts;
    const __nv_bfloat16* Wg = (FIRST ? g_w1s : g_w2s) + (size_t)e * KX * 1024;

    __shared__ __nv_bfloat16 As[2][BM][APAD];
    __shared__ __nv_bfloat16 Bs[2][BKS][BPAD];
    __shared__ int   srow[BM];
    __shared__ float sgate[BM];

    int tid = threadIdx.x;
    if (tid < BM) {
        int r = (tid < rows) ? tid : 0;
        int slot = off + row0 + r;
        srow[tid]  = FIRST ? g_slot_token[slot] : slot;
        sgate[tid] = g_slot_gate[slot];
    }
    __syncthreads();

    int lane = tid & 31, warp = tid >> 5;
    int wm = warp >> 2, wn = warp & 3;

    // global->smem chunk assignment (two 16B chunks each for A and B)
    int c1  = tid + 256;
    int rA0 = tid >> 2, kA0 = (tid & 3) * 8;
    int rA1 = c1  >> 2, kA1 = (c1  & 3) * 8;
    int rB0 = tid >> 4, nB0 = (tid & 15) * 8;
    int rB1 = c1  >> 4, nB1 = (c1  & 15) * 8;

    const size_t a0base = (size_t)srow[rA0] * KX;
    const size_t a1base = (size_t)srow[rA1] * KX;

    // ldmatrix per-lane base addresses
    int mrow = wm * 64 + (lane & 15);
    int kprt = (lane >> 4) * 8;
    int krow = lane & 15;
    int nprt = wn * 32 + (lane >> 4) * 8;
    uint32_t aAddr[2], bAddr[2];
    aAddr[0] = s2u(&As[0][mrow][kprt]);
    aAddr[1] = s2u(&As[1][mrow][kprt]);
    bAddr[0] = s2u(&Bs[0][krow][nprt]);
    bAddr[1] = s2u(&Bs[1][krow][nprt]);

    float acc[4][4][4];
#pragma unroll
    for (int i = 0; i < 4; i++)
#pragma unroll
        for (int j = 0; j < 4; j++)
#pragma unroll
            for (int q = 0; q < 4; q++) acc[i][j][q] = 0.f;

    // stage 0 load
    {
        uint4 va0 = *(const uint4*)(Ag + a0base + kA0);
        uint4 va1 = *(const uint4*)(Ag + a1base + kA1);
        uint4 vb0 = *(const uint4*)(Wg + (size_t)rB0 * 1024 + n0 + nB0);
        uint4 vb1 = *(const uint4*)(Wg + (size_t)rB1 * 1024 + n0 + nB1);
        *(uint2*)&As[0][rA0][kA0]     = make_uint2(va0.x, va0.y);
        *(uint2*)&As[0][rA0][kA0 + 4] = make_uint2(va0.z, va0.w);
        *(uint2*)&As[0][rA1][kA1]     = make_uint2(va1.x, va1.y);
        *(uint2*)&As[0][rA1][kA1 + 4] = make_uint2(va1.z, va1.w);
        *(uint4*)&Bs[0][rB0][nB0] = vb0;
        *(uint4*)&Bs[0][rB1][nB1] = vb1;
    }
    __syncthreads();

    int buf = 0;
    for (int s = 0; s < NSTAGE; s++) {
        uint4 va0, va1, vb0, vb1;
        if (s + 1 < NSTAGE) {
            int k0 = (s + 1) * BKS;
            int ak = (k0 < 2048) ? k0 : (k0 - 2048);   // A: [hi | lo | hi]
            int bk = (k0 < 1024) ? k0 : (k0 - 1024);   // B: [hi | hi | lo]
            va0 = *(const uint4*)(Ag + a0base + ak + kA0);
            va1 = *(const uint4*)(Ag + a1base + ak + kA1);
            vb0 = *(const uint4*)(Wg + (size_t)(bk + rB0) * 1024 + n0 + nB0);
            vb1 = *(const uint4*)(Wg + (size_t)(bk + rB1) * 1024 + n0 + nB1);
        }
#pragma unroll
        for (int ks = 0; ks < BKS; ks += 16) {
            uint32_t af[4][4], bq[2][4];
#pragma unroll
            for (int mi = 0; mi < 4; mi++) {
                uint32_t ad = aAddr[buf] + (uint32_t)((mi * 16 * APAD + ks) * 2);
                asm volatile("ldmatrix.sync.aligned.m8n8.x4.shared.b16 {%0,%1,%2,%3}, [%4];"
                    : "=r"(af[mi][0]), "=r"(af[mi][1]), "=r"(af[mi][2]), "=r"(af[mi][3])
                    : "r"(ad));
            }
#pragma unroll
            for (int np = 0; np < 2; np++) {
                uint32_t bd = bAddr[buf] + (uint32_t)((ks * BPAD + np * 16) * 2);
                asm volatile("ldmatrix.sync.aligned.m8n8.x4.trans.shared.b16 {%0,%1,%2,%3}, [%4];"
                    : "=r"(bq[np][0]), "=r"(bq[np][1]), "=r"(bq[np][2]), "=r"(bq[np][3])
                    : "r"(bd));
            }
#pragma unroll
            for (int mi = 0; mi < 4; mi++)
#pragma unroll
                for (int ni = 0; ni < 4; ni++) {
                    const uint32_t* b = &bq[ni >> 1][(ni & 1) * 2];
                    asm volatile("mma.sync.aligned.m16n8k16.row.col.f32.bf16.bf16.f32 "
                        "{%0,%1,%2,%3}, {%4,%5,%6,%7}, {%8,%9}, {%0,%1,%2,%3};"
                        : "+f"(acc[mi][ni][0]), "+f"(acc[mi][ni][1]),
                          "+f"(acc[mi][ni][2]), "+f"(acc[mi][ni][3])
                        : "r"(af[mi][0]), "r"(af[mi][1]), "r"(af[mi][2]), "r"(af[mi][3]),
                          "r"(b[0]), "r"(b[1]));
                }
        }
        if (s + 1 < NSTAGE) {
            buf ^= 1;
            *(uint2*)&As[buf][rA0][kA0]     = make_uint2(va0.x, va0.y);
            *(uint2*)&As[buf][rA0][kA0 + 4] = make_uint2(va0.z, va0.w);
            *(uint2*)&As[buf][rA1][kA1]     = make_uint2(va1.x, va1.y);
            *(uint2*)&As[buf][rA1][kA1 + 4] = make_uint2(va1.z, va1.w);
            *(uint4*)&Bs[buf][rB0][nB0] = vb0;
            *(uint4*)&Bs[buf][rB1][nB1] = vb1;
            __syncthreads();
        }
    }

    // epilogue
    int gr = lane >> 2;
    int gc = (lane & 3) * 2;
    float bv[4][2];
#pragma unroll
    for (int ni = 0; ni < 4; ni++) {
        int col = n0 + wn * 32 + ni * 8 + gc;
        bv[ni][0] = bias[e * 1024 + col];
        bv[ni][1] = bias[e * 1024 + col + 1];
    }
#pragma unroll
    for (int mi = 0; mi < 4; mi++)
#pragma unroll
        for (int jr = 0; jr < 2; jr++) {
            int r = wm * 64 + mi * 16 + gr + jr * 8;
            if (r < rows) {
                size_t slot = (size_t)(off + row0 + r);
                if (FIRST) {
#pragma unroll
                    for (int ni = 0; ni < 4; ni++) {
                        int col = n0 + wn * 32 + ni * 8 + gc;
                        float h0 = acc[mi][ni][jr * 2 + 0] + bv[ni][0];
                        float h1 = acc[mi][ni][jr * 2 + 1] + bv[ni][1];
                        float g0 = 0.5f * h0 * (1.f + erff(h0 * 0.70710678118654752f));
                        float g1 = 0.5f * h1 * (1.f + erff(h1 * 0.70710678118654752f));
                        __nv_bfloat16 h0b = __float2bfloat16(g0);
                        __nv_bfloat16 h1b = __float2bfloat16(g1);
                        __nv_bfloat16 l0b = __float2bfloat16(g0 - __bfloat162float(h0b));
                        __nv_bfloat16 l1b = __float2bfloat16(g1 - __bfloat162float(h1b));
                        *(__nv_bfloat162*)&g_acts[slot * KX + col]        = __halves2bfloat162(h0b, h1b);
                        *(__nv_bfloat162*)&g_acts[slot * KX + 1024 + col] = __halves2bfloat162(l0b, l1b);
                    }
                } else {
                    float gate = sgate[r];
#pragma unroll
                    for (int ni = 0; ni < 4; ni++) {
                        int col = n0 + wn * 32 + ni * 8 + gc;
                        float v0 = (acc[mi][ni][jr * 2 + 0] + bv[ni][0]) * gate;
                        float v1 = (acc[mi][ni][jr * 2 + 1] + bv[ni][1]) * gate;
                        *(float2*)&g_part[slot * DIM + col] = make_float2(v0, v1);
                    }
                }
            }
        }
}

// ---- combine: y[t] = part[slot0(t)] + part[slot1(t)] ----
__global__ void combine_kernel(float* __restrict__ y) {
    int i = blockIdx.x * blockDim.x + threadIdx.x;   // over NTOK*DIM/4
    int t  = i >> 8;
    int d4 = i & 255;
    int s0 = g_token_slot[t * 2];
    int s1 = g_token_slot[t * 2 + 1];
    const float4* p = (const float4*)g_part;
    float4 a = p[(size_t)s0 * 256 + d4];
    float4 b = p[(size_t)s1 * 256 + d4];
    ((float4*)y)[i] = make_float4(a.x + b.x, a.y + b.y, a.z + b.z, a.w + b.w);
}

extern "C" void kernel_launch(void* const* d_in, const int* in_sizes, int n_in,
                              void* d_out, int out_size) {
    const float* x  = (const float*)d_in[0];
    const float* w1 = (const float*)d_in[1];
    const float* b1 = (const float*)d_in[2];
    const float* w2 = (const float*)d_in[3];
    const float* b2 = (const float*)d_in[4];
    const float* wg = (const float*)d_in[5];
    float* y = (float*)d_out;

    zero_kernel<<<1, 32>>>();
    gating_kernel<<<NTOK / 8, 256>>>(x, wg);
    scan_kernel<<<1, 1>>>();
    build_kernel<<<NSLOT / 256, 256>>>();

    split_x_kernel<<<NTOK * DIM / 4 / 256, 256>>>(x);
    split_w_kernel<1><<<NE * DIM * HID / 4 / 256, 256>>>(w1);
    split_w_kernel<2><<<NE * HID * DIM / 4 / 256, 256>>>(w2);

    dim3 g1(HID / BN, NSLOT / BM, NE);   // static worst-case grid, early-exit on counts
    moe_gemm<true><<<g1, 256>>>(b1);

    dim3 g2(DIM / BN, NSLOT / BM, NE);
    moe_gemm<false><<<g2, 256>>>(b2);

    combine_kernel<<<NTOK * DIM / 4 / 256, 256>>>(y);
}